// round 10
// baseline (speedup 1.0000x reference)
#include <cuda_runtime.h>

#define DIM   4096
#define RANK  32
#define NEDIT 32            // B(4) * 8 edited rows

// ---------------------------------------------------------------------------
// Full per-row ReFT edit, isolated in a noinline function so its register
// pressure / scheduling cannot contaminate the copy path's load batching.
// One CTA (256 threads) handles one edited row.
// ---------------------------------------------------------------------------
__device__ __noinline__ void edit_row(
    const float* __restrict__ hs,
    const float* __restrict__ Wsrc, const float* __restrict__ bias,
    const float* __restrict__ Wproj,
    long base, float* __restrict__ out)
{
    __shared__ float4 xs4[DIM / 4];  // 16 KB
    __shared__ float  dots[2 * RANK];
    __shared__ float  s[RANK];

    const int tid = threadIdx.x;
    const float4* x4 = (const float4*)(hs + base);

    #pragma unroll
    for (int k = 0; k < 4; k++) {
        int i = tid + k * 256;
        xs4[i] = x4[i];
    }
    __syncthreads();

    // 64 dots: 8 warps x 8 dots, dual accumulators
    const int warp = tid >> 5;
    const int lane = tid & 31;
    #pragma unroll
    for (int k = 0; k < 8; k++) {
        const int di = warp * 8 + k;       // 0..63
        const float4* W4 = (const float4*)((di < RANK)
                               ? (Wsrc  + (long)di * DIM)
                               : (Wproj + (long)(di - RANK) * DIM));
        float acc0 = 0.f, acc1 = 0.f;
        #pragma unroll 4
        for (int i = lane; i < DIM / 4; i += 64) {
            float4 w0 = W4[i],      xv0 = xs4[i];
            float4 w1 = W4[i + 32], xv1 = xs4[i + 32];
            acc0 += w0.x * xv0.x + w0.y * xv0.y + w0.z * xv0.z + w0.w * xv0.w;
            acc1 += w1.x * xv1.x + w1.y * xv1.y + w1.z * xv1.z + w1.w * xv1.w;
        }
        float acc = acc0 + acc1;
        #pragma unroll
        for (int o = 16; o > 0; o >>= 1)
            acc += __shfl_xor_sync(0xffffffff, acc, o);
        if (lane == 0) dots[di] = acc;
    }
    __syncthreads();

    if (tid < RANK) {
        float src  = dots[tid] + bias[tid];
        float proj = dots[tid + RANK];
        s[tid] = (src > 0.f ? src : 0.f) - proj;
    }
    __syncthreads();

    float4* o4 = (float4*)(out + base);
    #pragma unroll
    for (int k = 0; k < 4; k++) {
        int i = tid + k * 256;
        float4 acc = xs4[i];
        #pragma unroll
        for (int r = 0; r < RANK; r++) {
            float4 w = ((const float4*)(Wproj + (long)r * DIM))[i];
            float sr = s[r];
            acc.x += sr * w.x;
            acc.y += sr * w.y;
            acc.z += sr * w.z;
            acc.w += sr * w.w;
        }
        o4[i] = acc;
    }
}

// ---------------------------------------------------------------------------
// Single kernel: bids 0..31 = edit CTAs (scheduled first, hidden under the
// copy wave); bids >= 32 = one copy CTA per row (R5's proven copy shape).
// ---------------------------------------------------------------------------
__global__ __launch_bounds__(256) void reft_kernel(
    const float* __restrict__ hs,
    const float* __restrict__ Wsrc_p, const float* __restrict__ bsrc_p,
    const float* __restrict__ Wproj_p,
    const float* __restrict__ Wsrc_s, const float* __restrict__ bsrc_s,
    const float* __restrict__ Wproj_s,
    const int* __restrict__ offsets, const int* __restrict__ seqlens,
    float* __restrict__ out)
{
    if (blockIdx.x >= NEDIT) {
        // -------- copy path: one CTA per row --------
        const int row = blockIdx.x - NEDIT;    // 0..16383
        const int tid = threadIdx.x;
        const int b = row >> 12;
        const int t = row & 4095;
        const int off = offsets[b];
        const int seq = seqlens[b];
        if (((unsigned)(t - off) < 4u) | ((unsigned)(t - (off + seq - 4)) < 4u))
            return;   // edited row: owned by an edit CTA

        const long base = (long)row * DIM;
        const float4* x4 = (const float4*)(hs + base);
        float4*       o4 = (float4*)(out + base);
        #pragma unroll
        for (int k = 0; k < 4; k++) {
            int i = tid + k * 256;
            o4[i] = x4[i];
        }
        return;
    }

    // -------- edit path --------
    const int j = blockIdx.x;        // 0..31
    const int b = j >> 3;
    const int slot = j & 7;
    int pos;
    const float *Wsrc, *bias, *Wproj;
    if (slot < 4) {
        pos = offsets[b] + slot;
        Wsrc = Wsrc_p; bias = bsrc_p; Wproj = Wproj_p;
    } else {
        pos = offsets[b] + seqlens[b] - 8 + slot;
        Wsrc = Wsrc_s; bias = bsrc_s; Wproj = Wproj_s;
    }
    const long base = ((long)b * 4096 + pos) * DIM;
    edit_row(hs, Wsrc, bias, Wproj, base, out);
}

extern "C" void kernel_launch(void* const* d_in, const int* in_sizes, int n_in,
                              void* d_out, int out_size) {
    const float* hs      = (const float*)d_in[0];
    const float* Wsrc_p  = (const float*)d_in[1];
    const float* bsrc_p  = (const float*)d_in[2];
    const float* Wproj_p = (const float*)d_in[3];
    const float* Wsrc_s  = (const float*)d_in[4];
    const float* bsrc_s  = (const float*)d_in[5];
    const float* Wproj_s = (const float*)d_in[6];
    const int*   offsets = (const int*)d_in[7];
    const int*   seqlens = (const int*)d_in[8];
    float* out = (float*)d_out;

    const int nrows = out_size / DIM;      // 16384
    reft_kernel<<<NEDIT + nrows, 256>>>(
        hs, Wsrc_p, bsrc_p, Wproj_p, Wsrc_s, bsrc_s, Wproj_s,
        offsets, seqlens, out);
}

// round 11
// speedup vs baseline: 1.0015x; 1.0015x over previous
#include <cuda_runtime.h>

#define DIM   4096
#define RANK  32
#define NEDIT 32            // B(4) * 8 edited rows

// ---------------------------------------------------------------------------
// Edit kernel: 32 CTAs, one per edited row. Fully self-contained (R1 logic).
// Fires griddepcontrol.launch_dependents at entry so the copy kernel
// (launched with ProgrammaticStreamSerialization) starts concurrently.
// ---------------------------------------------------------------------------
__global__ __launch_bounds__(256) void edit_kernel(
    const float* __restrict__ hs,
    const float* __restrict__ Wsrc_p, const float* __restrict__ bsrc_p,
    const float* __restrict__ Wproj_p,
    const float* __restrict__ Wsrc_s, const float* __restrict__ bsrc_s,
    const float* __restrict__ Wproj_s,
    const int* __restrict__ offsets, const int* __restrict__ seqlens,
    float* __restrict__ out)
{
    // Release the dependent (copy) kernel immediately.
    asm volatile("griddepcontrol.launch_dependents;");

    __shared__ float4 xs4[DIM / 4];  // 16 KB
    __shared__ float  dots[2 * RANK];
    __shared__ float  s[RANK];

    const int j = blockIdx.x;        // 0..31
    const int tid = threadIdx.x;
    const int b = j >> 3;
    const int slot = j & 7;
    int pos;
    const float *Wsrc, *bias, *Wproj;
    if (slot < 4) {
        pos = offsets[b] + slot;
        Wsrc = Wsrc_p; bias = bsrc_p; Wproj = Wproj_p;
    } else {
        pos = offsets[b] + seqlens[b] - 8 + slot;
        Wsrc = Wsrc_s; bias = bsrc_s; Wproj = Wproj_s;
    }

    const long base = ((long)b * 4096 + pos) * DIM;
    const float4* x4 = (const float4*)(hs + base);
    #pragma unroll
    for (int k = 0; k < 4; k++) {
        int i = tid + k * 256;
        xs4[i] = x4[i];
    }
    __syncthreads();

    // 64 dots: 8 warps x 8 dots, dual accumulators
    const int warp = tid >> 5;
    const int lane = tid & 31;
    #pragma unroll
    for (int k = 0; k < 8; k++) {
        const int di = warp * 8 + k;       // 0..63
        const float4* W4 = (const float4*)((di < RANK)
                               ? (Wsrc  + (long)di * DIM)
                               : (Wproj + (long)(di - RANK) * DIM));
        float acc0 = 0.f, acc1 = 0.f;
        #pragma unroll 4
        for (int i = lane; i < DIM / 4; i += 64) {
            float4 w0 = W4[i],      xv0 = xs4[i];
            float4 w1 = W4[i + 32], xv1 = xs4[i + 32];
            acc0 += w0.x * xv0.x + w0.y * xv0.y + w0.z * xv0.z + w0.w * xv0.w;
            acc1 += w1.x * xv1.x + w1.y * xv1.y + w1.z * xv1.z + w1.w * xv1.w;
        }
        float acc = acc0 + acc1;
        #pragma unroll
        for (int o = 16; o > 0; o >>= 1)
            acc += __shfl_xor_sync(0xffffffff, acc, o);
        if (lane == 0) dots[di] = acc;
    }
    __syncthreads();

    if (tid < RANK) {
        float src  = dots[tid] + bias[tid];
        float proj = dots[tid + RANK];
        s[tid] = (src > 0.f ? src : 0.f) - proj;
    }
    __syncthreads();

    float4* o4 = (float4*)(out + base);
    #pragma unroll
    for (int k = 0; k < 4; k++) {
        int i = tid + k * 256;
        float4 acc = xs4[i];
        #pragma unroll
        for (int r = 0; r < RANK; r++) {
            float4 w = ((const float4*)(Wproj + (long)r * DIM))[i];
            float sr = s[r];
            acc.x += sr * w.x;
            acc.y += sr * w.y;
            acc.z += sr * w.z;
            acc.w += sr * w.w;
        }
        o4[i] = acc;
    }
}

// ---------------------------------------------------------------------------
// Copy kernel: one CTA per row, skip edited rows (R5's proven 72% DRAM shape).
// Launched with ProgrammaticStreamSerialization -> overlaps edit_kernel.
// ---------------------------------------------------------------------------
__global__ __launch_bounds__(256) void copy_kernel(
    const float* __restrict__ hs,
    const int* __restrict__ offsets, const int* __restrict__ seqlens,
    float* __restrict__ out)
{
    const int row = blockIdx.x;            // 0..16383
    const int tid = threadIdx.x;
    const int b = row >> 12;
    const int t = row & 4095;
    const int off = offsets[b];
    const int seq = seqlens[b];

    if (((unsigned)(t - off) < 4u) | ((unsigned)(t - (off + seq - 4)) < 4u))
        return;   // edited row: owned by edit_kernel (disjoint writes)

    const long base = (long)row * DIM;
    const float4* x4 = (const float4*)(hs + base);
    float4*       o4 = (float4*)(out + base);
    #pragma unroll
    for (int k = 0; k < 4; k++) {
        int i = tid + k * 256;
        o4[i] = x4[i];
    }
}

extern "C" void kernel_launch(void* const* d_in, const int* in_sizes, int n_in,
                              void* d_out, int out_size) {
    const float* hs      = (const float*)d_in[0];
    const float* Wsrc_p  = (const float*)d_in[1];
    const float* bsrc_p  = (const float*)d_in[2];
    const float* Wproj_p = (const float*)d_in[3];
    const float* Wsrc_s  = (const float*)d_in[4];
    const float* bsrc_s  = (const float*)d_in[5];
    const float* Wproj_s = (const float*)d_in[6];
    const int*   offsets = (const int*)d_in[7];
    const int*   seqlens = (const int*)d_in[8];
    float* out = (float*)d_out;

    // 1) edit kernel (releases dependents at entry)
    edit_kernel<<<NEDIT, 256>>>(
        hs, Wsrc_p, bsrc_p, Wproj_p, Wsrc_s, bsrc_s, Wproj_s,
        offsets, seqlens, out);

    // 2) copy kernel with programmatic stream serialization -> overlaps (1)
    const int nrows = out_size / DIM;      // 16384
    cudaLaunchConfig_t cfg = {};
    cfg.gridDim  = dim3(nrows, 1, 1);
    cfg.blockDim = dim3(256, 1, 1);
    cfg.dynamicSmemBytes = 0;
    cfg.stream = 0;
    cudaLaunchAttribute attrs[1];
    attrs[0].id = cudaLaunchAttributeProgrammaticStreamSerialization;
    attrs[0].val.programmaticStreamSerializationAllowed = 1;
    cfg.attrs = attrs;
    cfg.numAttrs = 1;

    cudaError_t err = cudaLaunchKernelEx(&cfg, copy_kernel,
                                         hs, offsets, seqlens, out);
    if (err != cudaSuccess) {
        // Fallback: plain serialized launch (still correct)
        copy_kernel<<<nrows, 256>>>(hs, offsets, seqlens, out);
    }
}

// round 12
// speedup vs baseline: 1.1463x; 1.1446x over previous
#include <cuda_runtime.h>

#define DIM    4096
#define RANK   32
#define NROWS  32          // B(4) * 8 edited rows
#define NDOTS  64          // per row: 32 src + 32 proj
#define NSPLIT 4           // K-dim split per dot

// Partial dot products: [row j][dot di][split]
__device__ float g_part[NROWS * NDOTS * NSPLIT];

// ---------------------------------------------------------------------------
// dots: one warp per (edited row j, dot di, K-split). 1024 CTAs. (R5 shape,
// measured 8.9 us — launch/cold-DRAM floor, insensitive to further splitting)
// ---------------------------------------------------------------------------
__global__ __launch_bounds__(256) void dots_kernel(
    const float* __restrict__ hs,
    const float* __restrict__ Wsrc_p, const float* __restrict__ Wproj_p,
    const float* __restrict__ Wsrc_s, const float* __restrict__ Wproj_s,
    const int* __restrict__ offsets, const int* __restrict__ seqlens)
{
    const int warp = threadIdx.x >> 5;
    const int lane = threadIdx.x & 31;
    const int gw = blockIdx.x * 8 + warp;     // 0..8191
    const int j     = gw >> 8;                // 0..31
    const int di    = (gw >> 2) & 63;         // 0..63
    const int split = gw & 3;                 // 0..3

    const int b = j >> 3;
    const int slot = j & 7;
    int pos;
    const float *Wsrc, *Wproj;
    if (slot < 4) {
        pos = offsets[b] + slot;
        Wsrc = Wsrc_p; Wproj = Wproj_p;
    } else {
        pos = offsets[b] + seqlens[b] - 8 + slot;
        Wsrc = Wsrc_s; Wproj = Wproj_s;
    }

    const float4* x4 = (const float4*)(hs + ((long)b * 4096 + pos) * DIM);
    const float4* W4 = (const float4*)((di < RANK)
                           ? (Wsrc  + (long)di * DIM)
                           : (Wproj + (long)(di - RANK) * DIM));

    const int k0 = split * (DIM / 4 / NSPLIT);   // 256 float4 per split
    float acc = 0.f;
    #pragma unroll
    for (int k = 0; k < 8; k++) {
        const int i = k0 + lane + k * 32;
        float4 w  = W4[i];
        float4 xv = x4[i];
        acc += w.x * xv.x + w.y * xv.y + w.z * xv.z + w.w * xv.w;
    }
    #pragma unroll
    for (int o = 16; o > 0; o >>= 1)
        acc += __shfl_xor_sync(0xffffffff, acc, o);
    if (lane == 0) g_part[(j * NDOTS + di) * NSPLIT + split] = acc;
}

// ---------------------------------------------------------------------------
// copy: EXACT R11 copy_kernel — measured 76.26 us @ 79.6% DRAM standalone.
// One CTA per row; edited rows skipped (owned by apply_kernel).
// ---------------------------------------------------------------------------
__global__ __launch_bounds__(256) void copy_kernel(
    const float* __restrict__ hs,
    const int* __restrict__ offsets, const int* __restrict__ seqlens,
    float* __restrict__ out)
{
    const int row = blockIdx.x;            // 0..16383
    const int tid = threadIdx.x;
    const int b = row >> 12;
    const int t = row & 4095;
    const int off = offsets[b];
    const int seq = seqlens[b];

    if (((unsigned)(t - off) < 4u) | ((unsigned)(t - (off + seq - 4)) < 4u))
        return;   // edited row

    const long base = (long)row * DIM;
    const float4* x4 = (const float4*)(hs + base);
    float4*       o4 = (float4*)(out + base);
    #pragma unroll
    for (int k = 0; k < 4; k++) {
        int i = tid + k * 256;
        o4[i] = x4[i];
    }
}

// ---------------------------------------------------------------------------
// apply: one CTA per edited row; reduces g_part, writes x + s·Wproj.
// ---------------------------------------------------------------------------
__global__ __launch_bounds__(256) void apply_kernel(
    const float* __restrict__ hs,
    const float* __restrict__ bsrc_p, const float* __restrict__ Wproj_p,
    const float* __restrict__ bsrc_s, const float* __restrict__ Wproj_s,
    const int* __restrict__ offsets, const int* __restrict__ seqlens,
    float* __restrict__ out)
{
    const int j = blockIdx.x;              // 0..31
    const int tid = threadIdx.x;
    const int b = j >> 3;
    const int slot = j & 7;
    int pos;
    const float *bias, *Wproj;
    if (slot < 4) {
        pos = offsets[b] + slot;
        bias = bsrc_p; Wproj = Wproj_p;
    } else {
        pos = offsets[b] + seqlens[b] - 8 + slot;
        bias = bsrc_s; Wproj = Wproj_s;
    }

    __shared__ float s[RANK];
    if (tid < RANK) {
        const float* pp = &g_part[(j * NDOTS + tid) * NSPLIT];
        const float* qq = &g_part[(j * NDOTS + RANK + tid) * NSPLIT];
        float src  = pp[0] + pp[1] + pp[2] + pp[3] + bias[tid];
        float proj = qq[0] + qq[1] + qq[2] + qq[3];
        s[tid] = (src > 0.f ? src : 0.f) - proj;
    }
    __syncthreads();

    const long base = ((long)b * 4096 + pos) * DIM;
    const float4* x4 = (const float4*)(hs + base);
    float4*       o4 = (float4*)(out + base);
    #pragma unroll
    for (int k = 0; k < 4; k++) {
        int i = tid + k * 256;
        float4 acc = x4[i];
        #pragma unroll
        for (int r = 0; r < RANK; r++) {
            float4 w = ((const float4*)(Wproj + (long)r * DIM))[i];
            float sr = s[r];
            acc.x += sr * w.x;
            acc.y += sr * w.y;
            acc.z += sr * w.z;
            acc.w += sr * w.w;
        }
        o4[i] = acc;
    }
}

extern "C" void kernel_launch(void* const* d_in, const int* in_sizes, int n_in,
                              void* d_out, int out_size) {
    const float* hs      = (const float*)d_in[0];
    const float* Wsrc_p  = (const float*)d_in[1];
    const float* bsrc_p  = (const float*)d_in[2];
    const float* Wproj_p = (const float*)d_in[3];
    const float* Wsrc_s  = (const float*)d_in[4];
    const float* bsrc_s  = (const float*)d_in[5];
    const float* Wproj_s = (const float*)d_in[6];
    const int*   offsets = (const int*)d_in[7];
    const int*   seqlens = (const int*)d_in[8];
    float* out = (float*)d_out;

    dots_kernel<<<1024, 256>>>(hs, Wsrc_p, Wproj_p, Wsrc_s, Wproj_s,
                               offsets, seqlens);

    const int nrows = out_size / DIM;      // 16384
    copy_kernel<<<nrows, 256>>>(hs, offsets, seqlens, out);

    apply_kernel<<<NROWS, 256>>>(hs, bsrc_p, Wproj_p, bsrc_s, Wproj_s,
                                 offsets, seqlens, out);
}

// round 13
// speedup vs baseline: 1.3914x; 1.2138x over previous
#include <cuda_runtime.h>

#define DIM   4096
#define RANK  32
#define NEDIT 32            // B(4) * 8 edited rows

// ---------------------------------------------------------------------------
// Single kernel, two CTA roles:
//   bids 0..31      : self-contained per-row ReFT edit (hidden in copy wave)
//   bids 32..16415  : one copy CTA per row, edited rows skipped
// __launch_bounds__(256, 2): target 2 CTAs/SM -> reg ceiling ~128, so ptxas
// keeps the copy path's 4 float4 loads batched (MLP=4) instead of collapsing
// to regs=32 for occupancy (the R3/R10 failure mode).
// ---------------------------------------------------------------------------
__global__ __launch_bounds__(256, 2) void reft_kernel(
    const float* __restrict__ hs,
    const float* __restrict__ Wsrc_p, const float* __restrict__ bsrc_p,
    const float* __restrict__ Wproj_p,
    const float* __restrict__ Wsrc_s, const float* __restrict__ bsrc_s,
    const float* __restrict__ Wproj_s,
    const int* __restrict__ offsets, const int* __restrict__ seqlens,
    float* __restrict__ out)
{
    const int tid = threadIdx.x;

    if (blockIdx.x >= NEDIT) {
        // ---------------- copy path (R11's measured 76.3us shape) ----------
        const int row = blockIdx.x - NEDIT;    // 0..16383
        const int b = row >> 12;
        const int t = row & 4095;
        const int off = offsets[b];
        const int seq = seqlens[b];
        if (((unsigned)(t - off) < 4u) | ((unsigned)(t - (off + seq - 4)) < 4u))
            return;   // edited row: owned by an edit CTA

        const long base = (long)row * DIM;
        const float4* x4 = (const float4*)(hs + base);
        float4*       o4 = (float4*)(out + base);
        #pragma unroll
        for (int k = 0; k < 4; k++) {
            int i = tid + k * 256;
            o4[i] = x4[i];
        }
        return;
    }

    // ---------------- edit path: one CTA per edited row --------------------
    __shared__ float4 xs4[DIM / 4];  // 16 KB
    __shared__ float  dots[2 * RANK];
    __shared__ float  s[RANK];

    const int j = blockIdx.x;        // 0..31
    const int b = j >> 3;
    const int slot = j & 7;
    int pos;
    const float *Wsrc, *bias, *Wproj;
    if (slot < 4) {
        pos = offsets[b] + slot;
        Wsrc = Wsrc_p; bias = bsrc_p; Wproj = Wproj_p;
    } else {
        pos = offsets[b] + seqlens[b] - 8 + slot;
        Wsrc = Wsrc_s; bias = bsrc_s; Wproj = Wproj_s;
    }

    const long base = ((long)b * 4096 + pos) * DIM;
    const float4* x4 = (const float4*)(hs + base);
    #pragma unroll
    for (int k = 0; k < 4; k++) {
        int i = tid + k * 256;
        xs4[i] = x4[i];
    }
    __syncthreads();

    // 64 dots: 8 warps x 8 dots, dual accumulators
    const int warp = tid >> 5;
    const int lane = tid & 31;
    #pragma unroll
    for (int k = 0; k < 8; k++) {
        const int di = warp * 8 + k;       // 0..63
        const float4* W4 = (const float4*)((di < RANK)
                               ? (Wsrc  + (long)di * DIM)
                               : (Wproj + (long)(di - RANK) * DIM));
        float acc0 = 0.f, acc1 = 0.f;
        #pragma unroll 4
        for (int i = lane; i < DIM / 4; i += 64) {
            float4 w0 = W4[i],      xv0 = xs4[i];
            float4 w1 = W4[i + 32], xv1 = xs4[i + 32];
            acc0 += w0.x * xv0.x + w0.y * xv0.y + w0.z * xv0.z + w0.w * xv0.w;
            acc1 += w1.x * xv1.x + w1.y * xv1.y + w1.z * xv1.z + w1.w * xv1.w;
        }
        float acc = acc0 + acc1;
        #pragma unroll
        for (int o = 16; o > 0; o >>= 1)
            acc += __shfl_xor_sync(0xffffffff, acc, o);
        if (lane == 0) dots[di] = acc;
    }
    __syncthreads();

    if (tid < RANK) {
        float src  = dots[tid] + bias[tid];
        float proj = dots[tid + RANK];
        s[tid] = (src > 0.f ? src : 0.f) - proj;
    }
    __syncthreads();

    float4* o4 = (float4*)(out + base);
    #pragma unroll
    for (int k = 0; k < 4; k++) {
        int i = tid + k * 256;
        float4 acc = xs4[i];
        #pragma unroll
        for (int r = 0; r < RANK; r++) {
            float4 w = ((const float4*)(Wproj + (long)r * DIM))[i];
            float sr = s[r];
            acc.x += sr * w.x;
            acc.y += sr * w.y;
            acc.z += sr * w.z;
            acc.w += sr * w.w;
        }
        o4[i] = acc;
    }
}

extern "C" void kernel_launch(void* const* d_in, const int* in_sizes, int n_in,
                              void* d_out, int out_size) {
    const float* hs      = (const float*)d_in[0];
    const float* Wsrc_p  = (const float*)d_in[1];
    const float* bsrc_p  = (const float*)d_in[2];
    const float* Wproj_p = (const float*)d_in[3];
    const float* Wsrc_s  = (const float*)d_in[4];
    const float* bsrc_s  = (const float*)d_in[5];
    const float* Wproj_s = (const float*)d_in[6];
    const int*   offsets = (const int*)d_in[7];
    const int*   seqlens = (const int*)d_in[8];
    float* out = (float*)d_out;

    const int nrows = out_size / DIM;      // 16384
    reft_kernel<<<NEDIT + nrows, 256>>>(
        hs, Wsrc_p, bsrc_p, Wproj_p, Wsrc_s, bsrc_s, Wproj_s,
        offsets, seqlens, out);
}